// round 2
// baseline (speedup 1.0000x reference)
#include <cuda_runtime.h>

#define HH 64
#define WW 64
#define CI 256
#define CO 256
#define BB 8
#define KK 9
#define CK (CI*KK)   // 2304

typedef unsigned long long u64;

// ---------------- scratch (device globals; no allocation) ----------------
__device__ float  g_rwt[CI*KK*CO];     // reg_w transposed: [c][k][o]
__device__ float  g_awt[CI*KK*27];     // offset_w||mod_w transposed: [c][k][oc]
__device__ int4   g_idx[BB*HH*KK*WW];  // [b][h][k][w]: 4 clamped corner indices
__device__ float4 g_wgt[BB*HH*KK*WW];  // [b][h][k][w]: 4 bilinear wgts * mask * valid

// ---------------- packed f32x2 helpers (sm_103a FFMA2) ----------------
__device__ __forceinline__ u64 pack2f(float w) {
    u64 r; asm("mov.b64 %0, {%1, %1};" : "=l"(r) : "f"(w)); return r;
}
__device__ __forceinline__ void ffma2(u64 &d, u64 a, u64 b) {
    asm("fma.rn.f32x2 %0, %1, %2, %0;" : "+l"(d) : "l"(a), "l"(b));
}

// ---------------- kernel 0: weight transposes ----------------
__global__ __launch_bounds__(256) void k_transpose(
    const float* __restrict__ reg_w,
    const float* __restrict__ off_w,
    const float* __restrict__ mod_w)
{
    int i = blockIdx.x * 256 + threadIdx.x;
    if (i < CI*KK*CO) {
        int o = i & 255, ck = i >> 8;          // i = ck*256 + o
        g_rwt[i] = reg_w[o * CK + ck];
    }
    if (i < CI*KK*27) {
        int oc = i % 27, ck = i / 27;          // i = ck*27 + oc
        g_awt[i] = (oc < 18) ? off_w[oc * CK + ck] : mod_w[(oc-18) * CK + ck];
    }
}

// ---------------- kernel 1: offset/mod conv + sampling metadata ----------------
// one block per (b,h): 27 channels x 64 cols, then emit idx4/wgt4 per (k,s)
__global__ __launch_bounds__(256) void k_offsets(
    const float* __restrict__ x,
    const float* __restrict__ off_b,
    const float* __restrict__ mod_b)
{
    __shared__ float xs[3][72];        // rows h-1..h+1, cols -1..64 (zero padded)
    __shared__ float ws[243];          // [k][27]
    __shared__ float sconv[27*64];

    const int h = blockIdx.x, b = blockIdx.y;
    const int t = threadIdx.x;
    const int oc = t >> 3, sg = t & 7, s0 = sg << 3;
    const bool act = (t < 216);        // 27 oc * 8 s-groups

    float acc[8];
    float bias = 0.f;
    if (act) bias = (oc < 18) ? off_b[oc] : mod_b[oc - 18];
    #pragma unroll
    for (int j = 0; j < 8; j++) acc[j] = bias;

    const float* xb = x + (size_t)b * CI * HH * WW;

    for (int c = 0; c < CI; c++) {
        __syncthreads();
        if (t < 198) {
            int r = t / 66, cc = t % 66;
            int y = h - 1 + r, xc = cc - 1;
            float v = 0.f;
            if (y >= 0 && y < HH && xc >= 0 && xc < WW)
                v = xb[(c * HH + y) * WW + xc];
            xs[r][cc] = v;
        }
        if (t < 243) ws[t] = g_awt[c * 243 + t];
        __syncthreads();
        if (act) {
            float xr[3][10];
            #pragma unroll
            for (int r = 0; r < 3; r++)
                #pragma unroll
                for (int j = 0; j < 10; j++) xr[r][j] = xs[r][s0 + j];
            #pragma unroll
            for (int k = 0; k < 9; k++) {
                float w = ws[k * 27 + oc];
                int ky = k / 3, kx = k % 3;
                #pragma unroll
                for (int j = 0; j < 8; j++)
                    acc[j] = fmaf(w, xr[ky][kx + j], acc[j]);
            }
        }
    }
    __syncthreads();
    if (act) {
        #pragma unroll
        for (int j = 0; j < 8; j++) sconv[oc * 64 + s0 + j] = acc[j];
    }
    __syncthreads();

    const int base = ((b * HH + h) * KK) * WW;
    for (int e = t; e < KK * WW; e += 256) {
        int k = e >> 6, s = e & 63;
        float oy = sconv[(2*k    ) * 64 + s];
        float ox = sconv[(2*k + 1) * 64 + s];
        float mm = sconv[(18 + k ) * 64 + s];
        oy = fminf(fmaxf(oy, -16.f), 16.f);       // max_offset = 64/4
        ox = fminf(fmaxf(ox, -16.f), 16.f);
        mm = 1.f / (1.f + expf(-mm));              // sigmoid
        float py = oy + (float)(k / 3) + (float)(h - 1);
        float px = ox + (float)(k % 3) + (float)(s - 1);
        float y0f = floorf(py), x0f = floorf(px);
        float ly = py - y0f, lx = px - x0f;
        int y0 = (int)y0f, x0 = (int)x0f;
        int y1 = y0 + 1, x1 = x0 + 1;
        float vy0 = (y0 >= 0 && y0 < HH) ? 1.f : 0.f;
        float vy1 = (y1 >= 0 && y1 < HH) ? 1.f : 0.f;
        float vx0 = (x0 >= 0 && x0 < WW) ? 1.f : 0.f;
        float vx1 = (x1 >= 0 && x1 < WW) ? 1.f : 0.f;
        int iy0 = min(max(y0, 0), HH-1), iy1 = min(max(y1, 0), HH-1);
        int ix0 = min(max(x0, 0), WW-1), ix1 = min(max(x1, 0), WW-1);
        float w00 = (1.f-ly)*(1.f-lx)*mm*vy0*vx0;
        float w01 = (1.f-ly)*     lx *mm*vy0*vx1;
        float w10 =      ly *(1.f-lx)*mm*vy1*vx0;
        float w11 =      ly *     lx *mm*vy1*vx1;
        g_idx[base + e] = make_int4(iy0*WW+ix0, iy0*WW+ix1, iy1*WW+ix0, iy1*WW+ix1);
        g_wgt[base + e] = make_float4(w00, w01, w10, w11);
    }
}

// ---------------- kernel 2: main deform GEMM ----------------
// one block per (b,h): M=256 o x N=64 s, K=2304 (c x tap)
// 128 threads, each owns 16 o x 8 s (packed as 4 f32x2 per o)
__global__ __launch_bounds__(128, 2) void k_deform(
    const float* __restrict__ x, float* __restrict__ out)
{
    __shared__ int4   sIdx[576];
    __shared__ float4 sWgt[576];
    __shared__ float  sW[2304];   // [k][o]
    __shared__ float  sVal[576];  // [k][s]

    const int h = blockIdx.x, b = blockIdx.y;
    const int t = threadIdx.x;
    const int sg = t & 7, og = t >> 3;   // og: 0..15
    const int s0 = sg << 3;

    u64 acc[16][4];
    #pragma unroll
    for (int i = 0; i < 16; i++)
        #pragma unroll
        for (int j = 0; j < 4; j++) acc[i][j] = 0ull;

    {
        int base = ((b * HH + h) * KK) * WW;
        for (int i = t; i < 576; i += 128) {
            sIdx[i] = g_idx[base + i];
            sWgt[i] = g_wgt[base + i];
        }
    }

    const float4* rwt4 = (const float4*)g_rwt;
    const float*  xb   = x + (size_t)b * CI * HH * WW;

    for (int c = 0; c < CI; c++) {
        __syncthreads();   // prev consume done (and prologue visible at c=0)
        // stage weights for this c (coalesced from transposed copy)
        {
            float4* sW4 = (float4*)sW;
            #pragma unroll
            for (int i = 0; i < 5; i++) {
                int idx = t + i * 128;
                if (idx < 576) sW4[idx] = rwt4[c * 576 + idx];
            }
        }
        // produce bilinear-sampled values val[k][s]
        {
            const float* xp = xb + c * (HH * WW);
            #pragma unroll
            for (int i = 0; i < 5; i++) {
                int e = t + i * 128;
                if (e < 576) {
                    int4   id = sIdx[e];
                    float4 wg = sWgt[e];
                    float v = wg.x * __ldg(xp + id.x) + wg.y * __ldg(xp + id.y)
                            + wg.z * __ldg(xp + id.z) + wg.w * __ldg(xp + id.w);
                    sVal[e] = v;
                }
            }
        }
        __syncthreads();
        // consume: rank-9 update with packed f32x2 FMAs
        #pragma unroll
        for (int k = 0; k < 9; k++) {
            u64 v2[4];
            const u64* vp = (const u64*)&sVal[k * 64 + s0];
            #pragma unroll
            for (int j = 0; j < 4; j++) v2[j] = vp[j];
            float wv[16];
            const float4* wp = (const float4*)&sW[k * 256 + og * 16];
            *(float4*)&wv[ 0] = wp[0];
            *(float4*)&wv[ 4] = wp[1];
            *(float4*)&wv[ 8] = wp[2];
            *(float4*)&wv[12] = wp[3];
            #pragma unroll
            for (int oi = 0; oi < 16; oi++) {
                u64 w2 = pack2f(wv[oi]);
                #pragma unroll
                for (int j = 0; j < 4; j++) ffma2(acc[oi][j], w2, v2[j]);
            }
        }
    }

    // epilogue: out[b][o][h][s0..s0+7]
    #pragma unroll
    for (int oi = 0; oi < 16; oi++) {
        int o = og * 16 + oi;
        float* op = out + (((size_t)b * CO + o) * HH + h) * WW + s0;
        ulonglong2 p0, p1;
        p0.x = acc[oi][0]; p0.y = acc[oi][1];
        p1.x = acc[oi][2]; p1.y = acc[oi][3];
        ((ulonglong2*)op)[0] = p0;
        ((ulonglong2*)op)[1] = p1;
    }
}

// ---------------- launch ----------------
extern "C" void kernel_launch(void* const* d_in, const int* in_sizes, int n_in,
                              void* d_out, int out_size)
{
    const float* x     = (const float*)d_in[0];
    const float* off_w = (const float*)d_in[1];
    const float* off_b = (const float*)d_in[2];
    const float* mod_w = (const float*)d_in[3];
    const float* mod_b = (const float*)d_in[4];
    const float* reg_w = (const float*)d_in[5];
    float* out = (float*)d_out;

    k_transpose<<<(CI*KK*CO + 255) / 256, 256>>>(reg_w, off_w, mod_w);
    dim3 g(HH, BB);
    k_offsets<<<g, 256>>>(x, off_b, mod_b);
    k_deform <<<g, 128>>>(x, out);
}

// round 5
// speedup vs baseline: 1.3871x; 1.3871x over previous
#include <cuda_runtime.h>
#include <cstdint>

#define HH 64
#define WW 64
#define CI 256
#define CO 256
#define BB 8
#define KK 9
#define CK (CI*KK)      // 2304
#define NCHUNK 72
#define KC 32           // K per chunk
#define ASTR 40         // smem row stride (floats) for A/B operand tiles

// ---------------- scratch (device globals; no allocation) ----------------
__device__ float  g_awt[CK*27];          // offset_w||mod_w transposed: [ck][oc]
__device__ float  g_wt[CO*CK];           // tf32-rounded reg_w, [o][ck]
__device__ uint2  g_idx[BB*HH*KK*WW];    // packed 4 x u16 corner indices
__device__ float4 g_wgt[BB*HH*KK*WW];    // 4 bilinear wgts * mask * valid

// ---------------- helpers ----------------
__device__ __forceinline__ float to_tf32(float x) {
    float r; asm("cvt.rna.tf32.f32 %0, %1;" : "=f"(r) : "f"(x)); return r;
}
__device__ __forceinline__ void mma_tf32(float* d,
    uint32_t a0, uint32_t a1, uint32_t a2, uint32_t a3, uint32_t b0, uint32_t b1) {
    asm volatile("mma.sync.aligned.m16n8k8.row.col.f32.tf32.tf32.f32 "
        "{%0,%1,%2,%3}, {%4,%5,%6,%7}, {%8,%9}, {%0,%1,%2,%3};"
        : "+f"(d[0]), "+f"(d[1]), "+f"(d[2]), "+f"(d[3])
        : "r"(a0), "r"(a1), "r"(a2), "r"(a3), "r"(b0), "r"(b1));
}

// ---------------- kernel 0: weight prep ----------------
__global__ __launch_bounds__(256) void k_prep(
    const float* __restrict__ reg_w,
    const float* __restrict__ off_w,
    const float* __restrict__ mod_w)
{
    int i = blockIdx.x * 256 + threadIdx.x;
    if (i < CK*27) {
        int oc = i % 27, ck = i / 27;
        g_awt[i] = (oc < 18) ? off_w[oc * CK + ck] : mod_w[(oc-18) * CK + ck];
    }
    if (i < CO*CK) g_wt[i] = to_tf32(reg_w[i]);
}

// ---------------- kernel 1: offset/mod conv + sampling metadata ----------------
__global__ __launch_bounds__(256) void k_offsets(
    const float* __restrict__ x,
    const float* __restrict__ off_b,
    const float* __restrict__ mod_b)
{
    __shared__ float xs[4][3][72];
    __shared__ float ws[972];
    __shared__ float sconv[27*64];

    const int h = blockIdx.x, b = blockIdx.y;
    const int t = threadIdx.x;
    const int oc = t >> 3, sg = t & 7, s0 = sg << 3;
    const bool act = (t < 216);

    float acc[8];
    float bias = 0.f;
    if (act) bias = (oc < 18) ? off_b[oc] : mod_b[oc - 18];
    #pragma unroll
    for (int j = 0; j < 8; j++) acc[j] = bias;

    const float* xb = x + (size_t)b * CI * HH * WW;

    for (int c0 = 0; c0 < CI; c0 += 4) {
        __syncthreads();
        for (int e = t; e < 792; e += 256) {
            int cl = e / 198, rem = e - cl * 198;
            int r = rem / 66, col = rem - r * 66;
            int y = h - 1 + r, xc = col - 1;
            float v = 0.f;
            if (y >= 0 && y < HH && xc >= 0 && xc < WW)
                v = xb[((c0 + cl) * HH + y) * WW + xc];
            xs[cl][r][col] = v;
        }
        for (int e = t; e < 972; e += 256) ws[e] = g_awt[c0 * 243 + e];
        __syncthreads();
        if (act) {
            #pragma unroll
            for (int cl = 0; cl < 4; cl++) {
                float xr[3][10];
                #pragma unroll
                for (int r = 0; r < 3; r++)
                    #pragma unroll
                    for (int j = 0; j < 10; j++) xr[r][j] = xs[cl][r][s0 + j];
                #pragma unroll
                for (int k = 0; k < 9; k++) {
                    float w = ws[cl * 243 + k * 27 + oc];
                    int ky = k / 3, kx = k % 3;
                    #pragma unroll
                    for (int j = 0; j < 8; j++)
                        acc[j] = fmaf(w, xr[ky][kx + j], acc[j]);
                }
            }
        }
    }
    __syncthreads();
    if (act) {
        #pragma unroll
        for (int j = 0; j < 8; j++) sconv[oc * 64 + s0 + j] = acc[j];
    }
    __syncthreads();

    const int base = ((b * HH + h) * KK) * WW;
    for (int e = t; e < KK * WW; e += 256) {
        int k = e >> 6, s = e & 63;
        float oy = sconv[(2*k    ) * 64 + s];
        float ox = sconv[(2*k + 1) * 64 + s];
        float mm = sconv[(18 + k ) * 64 + s];
        oy = fminf(fmaxf(oy, -16.f), 16.f);
        ox = fminf(fmaxf(ox, -16.f), 16.f);
        mm = 1.f / (1.f + expf(-mm));
        float py = oy + (float)(k / 3) + (float)(h - 1);
        float px = ox + (float)(k % 3) + (float)(s - 1);
        float y0f = floorf(py), x0f = floorf(px);
        float ly = py - y0f, lx = px - x0f;
        int y0 = (int)y0f, x0 = (int)x0f;
        int y1 = y0 + 1, x1 = x0 + 1;
        float vy0 = (y0 >= 0 && y0 < HH) ? 1.f : 0.f;
        float vy1 = (y1 >= 0 && y1 < HH) ? 1.f : 0.f;
        float vx0 = (x0 >= 0 && x0 < WW) ? 1.f : 0.f;
        float vx1 = (x1 >= 0 && x1 < WW) ? 1.f : 0.f;
        unsigned iy0 = min(max(y0, 0), HH-1), iy1 = min(max(y1, 0), HH-1);
        unsigned ix0 = min(max(x0, 0), WW-1), ix1 = min(max(x1, 0), WW-1);
        float w00 = (1.f-ly)*(1.f-lx)*mm*vy0*vx0;
        float w01 = (1.f-ly)*     lx *mm*vy0*vx1;
        float w10 =      ly *(1.f-lx)*mm*vy1*vx0;
        float w11 =      ly *     lx *mm*vy1*vx1;
        g_idx[base + e] = make_uint2((iy0*WW+ix0) | ((iy0*WW+ix1) << 16),
                                     (iy1*WW+ix0) | ((iy1*WW+ix1) << 16));
        g_wgt[base + e] = make_float4(w00, w01, w10, w11);
    }
}

// ---------------- kernel 2: mma.sync tf32 deform GEMM ----------------
// CTA per (4 h-rows, o-half, b): D[s=256][o=128], K = 72 chunks x 32
// smem layout (dynamic)
#define SM_META_I 0                      // uint2[2304]  = 18432
#define SM_META_W 18432                  // float4[2304] = 36864
#define SM_A      55296                  // 2 * 256*40*4 = 81920
#define SM_B      137216                 // 2 * 128*40*4 = 40960
#define SM_TOT    178176

__global__ __launch_bounds__(512, 1) void k_deform(
    const float* __restrict__ x, float* __restrict__ out)
{
    extern __shared__ char smem[];
    uint2*  sI = (uint2*)(smem + SM_META_I);
    float4* sW = (float4*)(smem + SM_META_W);
    float*  sA = (float*)(smem + SM_A);
    float*  sB = (float*)(smem + SM_B);

    const int t  = threadIdx.x;
    const int b  = blockIdx.z;
    const int bo = blockIdx.y * 128;
    const int h0 = blockIdx.x * 4;

    // prologue: metadata into smem
    {
        const uint2*  gI = g_idx + (size_t)(b * HH + h0) * (KK * WW);
        const float4* gW = g_wgt + (size_t)(b * HH + h0) * (KK * WW);
        for (int e = t; e < 4 * KK * WW; e += 512) { sI[e] = gI[e]; sW[e] = gW[e]; }
    }

    const float* xb = x + (size_t)b * CI * HH * WW;

    // produce-role ids: thread -> (s, k-half)
    const int ps   = t >> 1;
    const int pkh  = (t & 1) * 16;
    const int pr9  = (ps >> 6) * 9;
    const int pwc  = ps & 63;
    const int sswz = 2 * (ps & 3);

    // B-staging ids: thread -> (o, k-quarter)
    const int so   = t >> 2;
    const int skq  = t & 3;
    const int oswz = 2 * (so & 3);

    // consume-role ids
    const int wid = t >> 5, lane = t & 31;
    const int mq = wid & 3, nq = wid >> 2;
    const int q  = lane >> 2, c2 = lane & 3;
    const int fswz = (2 * c2) ^ (2 * (q & 3));   // shared by A and B frag loads

    float acc[4][4][4];
    #pragma unroll
    for (int i = 0; i < 4; i++)
        #pragma unroll
        for (int j = 0; j < 4; j++)
            #pragma unroll
            for (int u = 0; u < 4; u++) acc[i][j][u] = 0.f;

    __syncthreads();   // metadata visible

    for (int i = 0; i <= NCHUNK; i++) {
        // ---- produce chunk i into buffer i&1 (issued first to hide LDG latency) ----
        if (i < NCHUNK) {
            const int p = i & 1;
            // stage B weights
            {
                float* Bb = sB + p * (128 * ASTR);
                const float* src = g_wt + (size_t)(bo + so) * CK + i * KC + skq * 8;
                float4 v0 = *(const float4*)(src);
                float4 v1 = *(const float4*)(src + 4);
                float vv[8] = {v0.x, v0.y, v0.z, v0.w, v1.x, v1.y, v1.z, v1.w};
                #pragma unroll
                for (int w = 0; w < 4; w++) {
                    int kp = skq * 8 + ((2 * w) ^ oswz);
                    *(float2*)&Bb[so * ASTR + kp] = make_float2(vv[w], vv[w + 4]);
                }
            }
            // gather-produce A values
            {
                float* Ab = sA + p * (256 * ASTR);
                const int kbase = i * KC + pkh;
                #pragma unroll
                for (int g = 0; g < 2; g++) {
                    #pragma unroll
                    for (int w = 0; w < 4; w++) {
                        float v[2];
                        #pragma unroll
                        for (int u = 0; u < 2; u++) {
                            int kg = kbase + g * 8 + w + u * 4;
                            int c = kg / 9;
                            int tap = kg - c * 9;
                            int m = (pr9 + tap) * 64 + pwc;
                            uint2 id = sI[m];
                            float4 wg = sW[m];
                            const float* xc = xb + (c << 12);
                            float s = wg.x * __ldg(xc + (id.x & 0xFFFF))
                                    + wg.y * __ldg(xc + (id.x >> 16))
                                    + wg.z * __ldg(xc + (id.y & 0xFFFF))
                                    + wg.w * __ldg(xc + (id.y >> 16));
                            v[u] = to_tf32(s);
                        }
                        int kp = pkh + g * 8 + ((2 * w) ^ sswz);
                        *(float2*)&Ab[ps * ASTR + kp] = make_float2(v[0], v[1]);
                    }
                }
            }
        }
        // ---- consume chunk i-1 from buffer (i-1)&1 ----
        if (i > 0) {
            const int p = (i - 1) & 1;
            const float* Ab = sA + p * (256 * ASTR);
            const float* Bb = sB + p * (128 * ASTR);
            #pragma unroll
            for (int ks = 0; ks < 4; ks++) {
                uint32_t af[4][4];
                #pragma unroll
                for (int mi = 0; mi < 4; mi++) {
                    int sr = mq * 64 + mi * 16 + q;
                    float2 lo = *(const float2*)&Ab[sr * ASTR + ks * 8 + fswz];
                    float2 hi = *(const float2*)&Ab[(sr + 8) * ASTR + ks * 8 + fswz];
                    af[mi][0] = __float_as_uint(lo.x);
                    af[mi][2] = __float_as_uint(lo.y);
                    af[mi][1] = __float_as_uint(hi.x);
                    af[mi][3] = __float_as_uint(hi.y);
                }
                uint32_t bf[4][2];
                #pragma unroll
                for (int nj = 0; nj < 4; nj++) {
                    int nr = nq * 32 + nj * 8 + q;
                    float2 bb = *(const float2*)&Bb[nr * ASTR + ks * 8 + fswz];
                    bf[nj][0] = __float_as_uint(bb.x);
                    bf[nj][1] = __float_as_uint(bb.y);
                }
                #pragma unroll
                for (int mi = 0; mi < 4; mi++)
                    #pragma unroll
                    for (int nj = 0; nj < 4; nj++)
                        mma_tf32(acc[mi][nj], af[mi][0], af[mi][1], af[mi][2], af[mi][3],
                                 bf[nj][0], bf[nj][1]);
            }
        }
        __syncthreads();
    }

    // ---- epilogue: C frags -> gmem ----
    #pragma unroll
    for (int mi = 0; mi < 4; mi++) {
        int wcol = mi * 16 + q;                 // w within row (r == mq)
        #pragma unroll
        for (int nj = 0; nj < 4; nj++) {
            int o = bo + nq * 32 + nj * 8 + 2 * c2;
            size_t base0 = ((size_t)(b * CO + o) * HH + h0 + mq) * WW;
            out[base0 + wcol]              = acc[mi][nj][0];
            out[base0 + 4096 + wcol]       = acc[mi][nj][1];   // o+1
            out[base0 + wcol + 8]          = acc[mi][nj][2];   // s+8
            out[base0 + 4096 + wcol + 8]   = acc[mi][nj][3];
        }
    }
}

// ---------------- launch ----------------
extern "C" void kernel_launch(void* const* d_in, const int* in_sizes, int n_in,
                              void* d_out, int out_size)
{
    const float* x     = (const float*)d_in[0];
    const float* off_w = (const float*)d_in[1];
    const float* off_b = (const float*)d_in[2];
    const float* mod_w = (const float*)d_in[3];
    const float* mod_b = (const float*)d_in[4];
    const float* reg_w = (const float*)d_in[5];
    float* out = (float*)d_out;

    cudaFuncSetAttribute(k_deform, cudaFuncAttributeMaxDynamicSharedMemorySize, SM_TOT);

    k_prep<<<(CO*CK + 255) / 256, 256>>>(reg_w, off_w, mod_w);
    dim3 g1(HH, BB);
    k_offsets<<<g1, 256>>>(x, off_b, mod_b);
    dim3 g2(16, 2, 8);
    k_deform<<<g2, 512, SM_TOT>>>(x, out);
}

// round 8
// speedup vs baseline: 1.4813x; 1.0679x over previous
#include <cuda_runtime.h>
#include <cstdint>

#define HH 64
#define WW 64
#define CI 256
#define CO 256
#define BB 8
#define KK 9
#define CK (CI*KK)      // 2304
#define NCHUNK 72
#define ASTR 40         // smem row stride (floats) for A/B operand tiles

// ---------------- scratch (device globals; no allocation) ----------------
__device__ float  g_wt[CO*CK];           // tf32-rounded reg_w, [o][ck]
__device__ float  g_owt[CK*32];          // tf32 offset/mod weights, [ck][oc-pad32]
__device__ uint2  g_idx[BB*HH*KK*WW];    // packed 4 x u16 corner indices
__device__ float4 g_wgt[BB*HH*KK*WW];    // 4 bilinear wgts * mask * valid

// ---------------- helpers ----------------
__device__ __forceinline__ float to_tf32(float x) {
    float r; asm("cvt.rna.tf32.f32 %0, %1;" : "=f"(r) : "f"(x)); return r;
}
__device__ __forceinline__ void mma_tf32(float* d,
    uint32_t a0, uint32_t a1, uint32_t a2, uint32_t a3, uint32_t b0, uint32_t b1) {
    asm volatile("mma.sync.aligned.m16n8k8.row.col.f32.tf32.tf32.f32 "
        "{%0,%1,%2,%3}, {%4,%5,%6,%7}, {%8,%9}, {%0,%1,%2,%3};"
        : "+f"(d[0]), "+f"(d[1]), "+f"(d[2]), "+f"(d[3])
        : "r"(a0), "r"(a1), "r"(a2), "r"(a3), "r"(b0), "r"(b1));
}
__device__ __forceinline__ int div9(int kg) { return (kg * 7282) >> 16; }   // kg < 2304

// ---------------- kernel 0: weight prep ----------------
__global__ __launch_bounds__(256) void k_prep(
    const float* __restrict__ reg_w,
    const float* __restrict__ off_w,
    const float* __restrict__ mod_w)
{
    int i = blockIdx.x * 256 + threadIdx.x;
    if (i < CO*CK) g_wt[i] = to_tf32(reg_w[i]);
    if (i < CK*32) {
        int oc = i & 31, ck = i >> 5;
        float v = 0.f;
        if (oc < 18)      v = off_w[oc * CK + ck];
        else if (oc < 27) v = mod_w[(oc - 18) * CK + ck];
        g_owt[i] = to_tf32(v);
    }
}

// ---------------- kernel 1: offset/mod conv (tf32 MMA) + sampling metadata ----
// CTA per (4 h-rows, b): D[m=256 (4r x 64w)][n=32 (27 oc)] , K = 72 chunks x 32
__global__ __launch_bounds__(256) void k_off(
    const float* __restrict__ x,
    const float* __restrict__ off_b,
    const float* __restrict__ mod_b)
{
    __shared__ float xs[5*6*68];     // 5 ch slots x 6 rows x 68 cols (zero-padded)
    __shared__ float wb[32*ASTR];    // W chunk [32k][40]
    __shared__ float sD[256*28];     // conv result dump

    const int t = threadIdx.x;
    const int h0 = blockIdx.x * 4, b = blockIdx.y;
    const int lane = t & 31, wid = t >> 5;
    const int q = lane >> 2, c2 = lane & 3;

    const float* xb = x + (size_t)b * CI * HH * WW;

    float acc[2][4][4];
    #pragma unroll
    for (int a = 0; a < 2; a++)
        #pragma unroll
        for (int c = 0; c < 4; c++)
            #pragma unroll
            for (int u = 0; u < 4; u++) acc[a][c][u] = 0.f;

    for (int i = 0; i < NCHUNK; i++) {
        __syncthreads();
        const int cbase = div9(32 * i);
        // stage 5 channels x 6 rows x 68 cols (cols shifted by +1, zero pad)
        #pragma unroll
        for (int j = 0; j < 8; j++) {
            int e = t + j * 256;
            if (e < 5*408) {                       // FIX: bound to xs extent
                int slot = e / 408, rem = e - slot * 408;
                int row6 = rem / 68, col = rem - row6 * 68;
                int c = cbase + slot;
                int y = h0 - 1 + row6, xc = col - 1;
                float v = 0.f;
                if (c < CI && y >= 0 && y < HH && xc >= 0 && xc < WW)
                    v = xb[((size_t)c * HH + y) * WW + xc];
                xs[e] = v;
            }
        }
        // stage W chunk
        #pragma unroll
        for (int j = 0; j < 4; j++) {
            int e = t + j * 256;
            int k = e >> 5, oc = e & 31;
            wb[k * ASTR + oc] = g_owt[(i * 32 + k) * 32 + oc];
        }
        __syncthreads();

        // per-thread k addresses for this chunk: k = 8ks + c2 (+4)
        int aoff[8];
        #pragma unroll
        for (int u = 0; u < 8; u++) {
            int kv = (u >> 1) * 8 + c2 + (u & 1) * 4;
            int kg = i * 32 + kv;
            int c = div9(kg), tap = kg - c * 9;
            int ky = (tap * 11) >> 5, kx = tap - 3 * ky;
            aoff[u] = (c - cbase) * 408 + ky * 68 + kx;
        }

        #pragma unroll
        for (int ks = 0; ks < 4; ks++) {
            uint32_t af[2][4];
            #pragma unroll
            for (int mi = 0; mi < 2; mi++) {
                int m0 = wid * 32 + mi * 16;
                int base = (m0 >> 6) * 68 + (m0 & 63) + q;
                af[mi][0] = __float_as_uint(to_tf32(xs[aoff[2*ks]     + base]));
                af[mi][1] = __float_as_uint(to_tf32(xs[aoff[2*ks]     + base + 8]));
                af[mi][2] = __float_as_uint(to_tf32(xs[aoff[2*ks + 1] + base]));
                af[mi][3] = __float_as_uint(to_tf32(xs[aoff[2*ks + 1] + base + 8]));
            }
            uint32_t bf[4][2];
            #pragma unroll
            for (int nj = 0; nj < 4; nj++) {
                int n = nj * 8 + q;
                bf[nj][0] = __float_as_uint(wb[(8*ks + c2)     * ASTR + n]);
                bf[nj][1] = __float_as_uint(wb[(8*ks + c2 + 4) * ASTR + n]);
            }
            #pragma unroll
            for (int mi = 0; mi < 2; mi++)
                #pragma unroll
                for (int nj = 0; nj < 4; nj++)
                    mma_tf32(acc[mi][nj], af[mi][0], af[mi][1], af[mi][2], af[mi][3],
                             bf[nj][0], bf[nj][1]);
        }
    }

    __syncthreads();
    // dump D (+bias) to smem
    #pragma unroll
    for (int mi = 0; mi < 2; mi++) {
        #pragma unroll
        for (int nj = 0; nj < 4; nj++) {
            int m = wid * 32 + mi * 16 + q;
            int oc = nj * 8 + 2 * c2;
            if (oc < 28) {
                float b0 = (oc < 18) ? off_b[oc] : ((oc < 27) ? mod_b[oc - 18] : 0.f);
                int oc1 = oc + 1;
                float b1 = (oc1 < 18) ? off_b[oc1] : ((oc1 < 27) ? mod_b[oc1 - 18] : 0.f);
                sD[m * 28 + oc]           = acc[mi][nj][0] + b0;
                if (oc1 < 28) sD[m * 28 + oc1] = acc[mi][nj][1] + b1;
                sD[(m + 8) * 28 + oc]     = acc[mi][nj][2] + b0;
                if (oc1 < 28) sD[(m + 8) * 28 + oc1] = acc[mi][nj][3] + b1;
            }
        }
    }
    __syncthreads();

    // metadata epilogue: 4 rows x 9 taps x 64 w
    #pragma unroll
    for (int j = 0; j < 9; j++) {
        int e = t + j * 256;               // < 2304
        int r = e / 576, rem = e - r * 576;
        int k = rem >> 6, s = rem & 63;
        int m = r * 64 + s;
        float oy = sD[m * 28 + 2*k];
        float ox = sD[m * 28 + 2*k + 1];
        float mm = sD[m * 28 + 18 + k];
        oy = fminf(fmaxf(oy, -16.f), 16.f);
        ox = fminf(fmaxf(ox, -16.f), 16.f);
        mm = 1.f / (1.f + expf(-mm));
        float py = oy + (float)(k / 3) + (float)(h0 + r - 1);
        float px = ox + (float)(k % 3) + (float)(s - 1);
        float y0f = floorf(py), x0f = floorf(px);
        float ly = py - y0f, lx = px - x0f;
        int y0 = (int)y0f, x0 = (int)x0f;
        int y1 = y0 + 1, x1 = x0 + 1;
        float vy0 = (y0 >= 0 && y0 < HH) ? 1.f : 0.f;
        float vy1 = (y1 >= 0 && y1 < HH) ? 1.f : 0.f;
        float vx0 = (x0 >= 0 && x0 < WW) ? 1.f : 0.f;
        float vx1 = (x1 >= 0 && x1 < WW) ? 1.f : 0.f;
        unsigned iy0 = min(max(y0, 0), HH-1), iy1 = min(max(y1, 0), HH-1);
        unsigned ix0 = min(max(x0, 0), WW-1), ix1 = min(max(x1, 0), WW-1);
        float w00 = (1.f-ly)*(1.f-lx)*mm*vy0*vx0;
        float w01 = (1.f-ly)*     lx *mm*vy0*vx1;
        float w10 =      ly *(1.f-lx)*mm*vy1*vx0;
        float w11 =      ly *     lx *mm*vy1*vx1;
        size_t g = ((size_t)(b * HH + h0 + r) * KK + k) * WW + s;
        g_idx[g] = make_uint2((iy0*WW+ix0) | ((iy0*WW+ix1) << 16),
                              (iy1*WW+ix0) | ((iy1*WW+ix1) << 16));
        g_wgt[g] = make_float4(w00, w01, w10, w11);
    }
}

// ---------------- kernel 2: mma.sync tf32 deform GEMM ----------------
// CTA per (2 h-rows, o-half, b): D[m=128 (2r x 64w)][n=128 o], 2 CTAs/SM
#define SMI  0                       // uint2[18*68]  = 9792
#define SMW  9792                    // float4[18*68] = 19584
#define SMA  29376                   // 2 * 128*40*4  = 40960
#define SMB  70336                   // 2 * 128*40*4  = 40960
#define SMT  111296

__global__ __launch_bounds__(256, 2) void k_deform(
    const float* __restrict__ x, float* __restrict__ out)
{
    extern __shared__ char smem[];
    uint2*  sI = (uint2*)(smem + SMI);
    float4* sW = (float4*)(smem + SMW);
    float*  sA = (float*)(smem + SMA);
    float*  sB = (float*)(smem + SMB);

    const int t = threadIdx.x;
    const int b = blockIdx.z;
    const int bo = blockIdx.y * 128;
    const int h0 = blockIdx.x * 2;
    const int lane = t & 31, wid = t >> 5;
    const int q = lane >> 2, c2 = lane & 3;

    // prologue: metadata rows h0, h0+1 into smem (stride 68)
    for (int e = t; e < 2 * KK * WW; e += 256) {
        int rt = e >> 6, w = e & 63;
        int r = rt >= 9;
        int tap = rt - 9 * r;
        size_t g = ((size_t)(b * HH + h0 + r) * KK + tap) * WW + w;
        sI[rt * 68 + w] = g_idx[g];
        sW[rt * 68 + w] = g_wgt[g];
    }

    const float* xb = x + (size_t)b * CI * HH * WW;

    // consume ids
    const int mq = wid & 3, nq = wid >> 2;
    const int fswz = (2 * c2) ^ (2 * (q & 3));

    // produce ids: warp wid owns k-quad [wid*4, wid*4+4); lane -> (wo, kk)
    const int wo = lane >> 2;          // 8 w per octet
    const int kk = lane & 3;
    const int kchunk = wid * 4 + kk;   // k within chunk (0..31), fixed per thread
    const int grp = kchunk >> 3, kk8 = kchunk & 7;
    const int posbase = grp * 8 + (kk8 >> 2);
    const int posx = (2 * (kk8 & 3)) ^ (2 * (wo & 3));
    const int pos = posbase + posx;

    // B stage ids
    const int so = t >> 1, skh = (t & 1) * 16;
    const int obank = 2 * (so & 3);

    float acc[2][8][4];
    #pragma unroll
    for (int a = 0; a < 2; a++)
        #pragma unroll
        for (int c = 0; c < 8; c++)
            #pragma unroll
            for (int u = 0; u < 4; u++) acc[a][c][u] = 0.f;

    __syncthreads();

    for (int i = 0; i <= NCHUNK; i++) {
        // ---- consume chunk i-1 ----
        if (i > 0) {
            const int p = (i - 1) & 1;
            const float* Ab = sA + p * (128 * ASTR);
            const float* Bb = sB + p * (128 * ASTR);
            #pragma unroll
            for (int ks = 0; ks < 4; ks++) {
                uint32_t af[2][4];
                #pragma unroll
                for (int mi = 0; mi < 2; mi++) {
                    int sr = mq * 32 + mi * 16 + q;
                    float2 lo = *(const float2*)&Ab[sr * ASTR + ks * 8 + fswz];
                    float2 hi = *(const float2*)&Ab[(sr + 8) * ASTR + ks * 8 + fswz];
                    af[mi][0] = __float_as_uint(lo.x);
                    af[mi][2] = __float_as_uint(lo.y);
                    af[mi][1] = __float_as_uint(hi.x);
                    af[mi][3] = __float_as_uint(hi.y);
                }
                uint32_t bf[8][2];
                #pragma unroll
                for (int nj = 0; nj < 8; nj++) {
                    int nr = nq * 64 + nj * 8 + q;
                    float2 bb = *(const float2*)&Bb[nr * ASTR + ks * 8 + fswz];
                    bf[nj][0] = __float_as_uint(bb.x);
                    bf[nj][1] = __float_as_uint(bb.y);
                }
                #pragma unroll
                for (int mi = 0; mi < 2; mi++)
                    #pragma unroll
                    for (int nj = 0; nj < 8; nj++)
                        mma_tf32(acc[mi][nj], af[mi][0], af[mi][1], af[mi][2], af[mi][3],
                                 bf[nj][0], bf[nj][1]);
            }
        }
        // ---- produce chunk i ----
        if (i < NCHUNK) {
            const int p = i & 1;
            // B: weights, pair-packed
            {
                float* Bb = sB + p * (128 * ASTR);
                const float* src = g_wt + (size_t)(bo + so) * CK + i * 32 + skh;
                float4 v0 = *(const float4*)(src);
                float4 v1 = *(const float4*)(src + 4);
                float4 v2 = *(const float4*)(src + 8);
                float4 v3 = *(const float4*)(src + 12);
                float g0[8] = {v0.x, v0.y, v0.z, v0.w, v1.x, v1.y, v1.z, v1.w};
                float g1[8] = {v2.x, v2.y, v2.z, v2.w, v3.x, v3.y, v3.z, v3.w};
                #pragma unroll
                for (int w4 = 0; w4 < 4; w4++) {
                    int kp = ((2 * w4) ^ obank);
                    *(float2*)&Bb[so * ASTR + skh + kp]     = make_float2(g0[w4], g0[w4 + 4]);
                    *(float2*)&Bb[so * ASTR + skh + 8 + kp] = make_float2(g1[w4], g1[w4 + 4]);
                }
            }
            // A: gather-produce
            {
                float* Ab = sA + p * (128 * ASTR);
                const int kg = i * 32 + kchunk;
                const int c = div9(kg), tap = kg - c * 9;
                const float* xc = xb + ((size_t)c << 12);
                const int tap68 = tap * 68;
                #pragma unroll
                for (int jj = 0; jj < 16; jj++) {
                    int r = jj >> 3, wg = jj & 7;
                    int w = wg * 8 + wo;
                    int midx = r * 612 + tap68 + w;
                    uint2  id = sI[midx];
                    float4 wg4 = sW[midx];
                    float v = wg4.x * __ldg(xc + (id.x & 0xFFFF))
                            + wg4.y * __ldg(xc + (id.x >> 16))
                            + wg4.z * __ldg(xc + (id.y & 0xFFFF))
                            + wg4.w * __ldg(xc + (id.y >> 16));
                    int m = r * 64 + w;
                    Ab[m * ASTR + pos] = to_tf32(v);
                }
            }
        }
        __syncthreads();
    }

    // ---- epilogue ----
    #pragma unroll
    for (int mi = 0; mi < 2; mi++) {
        #pragma unroll
        for (int nj = 0; nj < 8; nj++) {
            int m = mq * 32 + mi * 16 + q;
            int o = bo + nq * 64 + nj * 8 + 2 * c2;
            #pragma unroll
            for (int half = 0; half < 2; half++) {
                int mm = m + half * 8;
                int r = mm >> 6, w = mm & 63;
                size_t base = ((size_t)(b * CO + o) * HH + h0 + r) * WW + w;
                out[base]        = acc[mi][nj][half * 2];
                out[base + 4096] = acc[mi][nj][half * 2 + 1];   // o+1
            }
        }
    }
}

// ---------------- launch ----------------
extern "C" void kernel_launch(void* const* d_in, const int* in_sizes, int n_in,
                              void* d_out, int out_size)
{
    const float* x     = (const float*)d_in[0];
    const float* off_w = (const float*)d_in[1];
    const float* off_b = (const float*)d_in[2];
    const float* mod_w = (const float*)d_in[3];
    const float* mod_b = (const float*)d_in[4];
    const float* reg_w = (const float*)d_in[5];
    float* out = (float*)d_out;

    cudaFuncSetAttribute(k_deform, cudaFuncAttributeMaxDynamicSharedMemorySize, SMT);

    k_prep<<<(CO*CK + 255) / 256, 256>>>(reg_w, off_w, mod_w);
    dim3 g1(16, 8);
    k_off<<<g1, 256>>>(x, off_b, mod_b);
    dim3 g2(32, 2, 8);
    k_deform<<<g2, 256, SMT>>>(x, out);
}

// round 9
// speedup vs baseline: 1.8492x; 1.2484x over previous
#include <cuda_runtime.h>
#include <cstdint>

#define HH 64
#define WW 64
#define CI 256
#define CO 256
#define BB 8
#define KK 9
#define CK (CI*KK)      // 2304
#define NCHUNK 72
#define ASTR 40         // k_off smem stride
#define GSTR 140        // k_gemm smem row stride (floats)

// ---------------- scratch (device globals; no allocation) ----------------
__device__ float  g_owt[CK*32];              // tf32 offset/mod weights, [ck][oc-pad32]
__device__ float  g_wtT[CK*CO];              // tf32 reg_w transposed: [ck][o]
__device__ uint2  g_idx[BB*HH*KK*WW];        // packed 4 x u16 corner indices (y*64+x)
__device__ float4 g_wgt[BB*HH*KK*WW];        // 4 bilinear wgts * mask * valid
__device__ float  g_val[(size_t)BB*CK*4096]; // gathered A: [b][ck][s], tf32

// ---------------- helpers ----------------
__device__ __forceinline__ float to_tf32(float x) {
    float r; asm("cvt.rna.tf32.f32 %0, %1;" : "=f"(r) : "f"(x)); return r;
}
__device__ __forceinline__ void mma_tf32(float* d,
    uint32_t a0, uint32_t a1, uint32_t a2, uint32_t a3, uint32_t b0, uint32_t b1) {
    asm volatile("mma.sync.aligned.m16n8k8.row.col.f32.tf32.tf32.f32 "
        "{%0,%1,%2,%3}, {%4,%5,%6,%7}, {%8,%9}, {%0,%1,%2,%3};"
        : "+f"(d[0]), "+f"(d[1]), "+f"(d[2]), "+f"(d[3])
        : "r"(a0), "r"(a1), "r"(a2), "r"(a3), "r"(b0), "r"(b1));
}
__device__ __forceinline__ int div9(int kg) { return (kg * 7282) >> 16; }   // kg < 2304
__device__ __forceinline__ uint32_t smem_u32(const void* p) {
    uint32_t a;
    asm("{ .reg .u64 t; cvta.to.shared.u64 t, %1; cvt.u32.u64 %0, t; }" : "=r"(a) : "l"(p));
    return a;
}
#define CP_ASYNC16(sa, ga) asm volatile("cp.async.cg.shared.global [%0], [%1], 16;" :: "r"(sa), "l"(ga))
#define CP_COMMIT()        asm volatile("cp.async.commit_group;" ::: "memory")
#define CP_WAIT1()         asm volatile("cp.async.wait_group 1;" ::: "memory")
#define CP_WAIT0()         asm volatile("cp.async.wait_group 0;" ::: "memory")

// ---------------- kernel 0: weight prep ----------------
__global__ __launch_bounds__(256) void k_prep(
    const float* __restrict__ reg_w,
    const float* __restrict__ off_w,
    const float* __restrict__ mod_w)
{
    int i = blockIdx.x * 256 + threadIdx.x;
    if (i < CK*CO) {                       // i = ck*256 + o
        int o = i & 255, ck = i >> 8;
        g_wtT[i] = to_tf32(reg_w[o * CK + ck]);
    }
    if (i < CK*32) {
        int oc = i & 31, ck = i >> 5;
        float v = 0.f;
        if (oc < 18)      v = off_w[oc * CK + ck];
        else if (oc < 27) v = mod_w[(oc - 18) * CK + ck];
        g_owt[i] = to_tf32(v);
    }
}

// ---------------- kernel 1: offset/mod conv (tf32 MMA) + sampling metadata ----
__global__ __launch_bounds__(256) void k_off(
    const float* __restrict__ x,
    const float* __restrict__ off_b,
    const float* __restrict__ mod_b)
{
    __shared__ float xs[5*6*68];
    __shared__ float wb[32*ASTR];
    __shared__ float sD[256*28];

    const int t = threadIdx.x;
    const int h0 = blockIdx.x * 4, b = blockIdx.y;
    const int lane = t & 31, wid = t >> 5;
    const int q = lane >> 2, c2 = lane & 3;

    const float* xb = x + (size_t)b * CI * HH * WW;

    float acc[2][4][4];
    #pragma unroll
    for (int a = 0; a < 2; a++)
        #pragma unroll
        for (int c = 0; c < 4; c++)
            #pragma unroll
            for (int u = 0; u < 4; u++) acc[a][c][u] = 0.f;

    for (int i = 0; i < NCHUNK; i++) {
        __syncthreads();
        const int cbase = div9(32 * i);
        #pragma unroll
        for (int j = 0; j < 8; j++) {
            int e = t + j * 256;
            if (e < 5*408) {
                int slot = e / 408, rem = e - slot * 408;
                int row6 = rem / 68, col = rem - row6 * 68;
                int c = cbase + slot;
                int y = h0 - 1 + row6, xc = col - 1;
                float v = 0.f;
                if (c < CI && y >= 0 && y < HH && xc >= 0 && xc < WW)
                    v = xb[((size_t)c * HH + y) * WW + xc];
                xs[e] = v;
            }
        }
        #pragma unroll
        for (int j = 0; j < 4; j++) {
            int e = t + j * 256;
            int k = e >> 5, oc = e & 31;
            wb[k * ASTR + oc] = g_owt[(i * 32 + k) * 32 + oc];
        }
        __syncthreads();

        int aoff[8];
        #pragma unroll
        for (int u = 0; u < 8; u++) {
            int kv = (u >> 1) * 8 + c2 + (u & 1) * 4;
            int kg = i * 32 + kv;
            int c = div9(kg), tap = kg - c * 9;
            int ky = (tap * 11) >> 5, kx = tap - 3 * ky;
            aoff[u] = (c - cbase) * 408 + ky * 68 + kx;
        }

        #pragma unroll
        for (int ks = 0; ks < 4; ks++) {
            uint32_t af[2][4];
            #pragma unroll
            for (int mi = 0; mi < 2; mi++) {
                int m0 = wid * 32 + mi * 16;
                int base = (m0 >> 6) * 68 + (m0 & 63) + q;
                af[mi][0] = __float_as_uint(to_tf32(xs[aoff[2*ks]     + base]));
                af[mi][1] = __float_as_uint(to_tf32(xs[aoff[2*ks]     + base + 8]));
                af[mi][2] = __float_as_uint(to_tf32(xs[aoff[2*ks + 1] + base]));
                af[mi][3] = __float_as_uint(to_tf32(xs[aoff[2*ks + 1] + base + 8]));
            }
            uint32_t bf[4][2];
            #pragma unroll
            for (int nj = 0; nj < 4; nj++) {
                int n = nj * 8 + q;
                bf[nj][0] = __float_as_uint(wb[(8*ks + c2)     * ASTR + n]);
                bf[nj][1] = __float_as_uint(wb[(8*ks + c2 + 4) * ASTR + n]);
            }
            #pragma unroll
            for (int mi = 0; mi < 2; mi++)
                #pragma unroll
                for (int nj = 0; nj < 4; nj++)
                    mma_tf32(acc[mi][nj], af[mi][0], af[mi][1], af[mi][2], af[mi][3],
                             bf[nj][0], bf[nj][1]);
        }
    }

    __syncthreads();
    #pragma unroll
    for (int mi = 0; mi < 2; mi++) {
        #pragma unroll
        for (int nj = 0; nj < 4; nj++) {
            int m = wid * 32 + mi * 16 + q;
            int oc = nj * 8 + 2 * c2;
            if (oc < 28) {
                float b0 = (oc < 18) ? off_b[oc] : ((oc < 27) ? mod_b[oc - 18] : 0.f);
                int oc1 = oc + 1;
                float b1 = (oc1 < 18) ? off_b[oc1] : ((oc1 < 27) ? mod_b[oc1 - 18] : 0.f);
                sD[m * 28 + oc]           = acc[mi][nj][0] + b0;
                if (oc1 < 28) sD[m * 28 + oc1] = acc[mi][nj][1] + b1;
                sD[(m + 8) * 28 + oc]     = acc[mi][nj][2] + b0;
                if (oc1 < 28) sD[(m + 8) * 28 + oc1] = acc[mi][nj][3] + b1;
            }
        }
    }
    __syncthreads();

    #pragma unroll
    for (int j = 0; j < 9; j++) {
        int e = t + j * 256;
        int r = e / 576, rem = e - r * 576;
        int k = rem >> 6, s = rem & 63;
        int m = r * 64 + s;
        float oy = sD[m * 28 + 2*k];
        float ox = sD[m * 28 + 2*k + 1];
        float mm = sD[m * 28 + 18 + k];
        oy = fminf(fmaxf(oy, -16.f), 16.f);
        ox = fminf(fmaxf(ox, -16.f), 16.f);
        mm = 1.f / (1.f + expf(-mm));
        float py = oy + (float)(k / 3) + (float)(h0 + r - 1);
        float px = ox + (float)(k % 3) + (float)(s - 1);
        float y0f = floorf(py), x0f = floorf(px);
        float ly = py - y0f, lx = px - x0f;
        int y0 = (int)y0f, x0 = (int)x0f;
        int y1 = y0 + 1, x1 = x0 + 1;
        float vy0 = (y0 >= 0 && y0 < HH) ? 1.f : 0.f;
        float vy1 = (y1 >= 0 && y1 < HH) ? 1.f : 0.f;
        float vx0 = (x0 >= 0 && x0 < WW) ? 1.f : 0.f;
        float vx1 = (x1 >= 0 && x1 < WW) ? 1.f : 0.f;
        unsigned iy0 = min(max(y0, 0), HH-1), iy1 = min(max(y1, 0), HH-1);
        unsigned ix0 = min(max(x0, 0), WW-1), ix1 = min(max(x1, 0), WW-1);
        float w00 = (1.f-ly)*(1.f-lx)*mm*vy0*vx0;
        float w01 = (1.f-ly)*     lx *mm*vy0*vx1;
        float w10 =      ly *(1.f-lx)*mm*vy1*vx0;
        float w11 =      ly *     lx *mm*vy1*vx1;
        size_t g = ((size_t)(b * HH + h0 + r) * KK + k) * WW + s;
        g_idx[g] = make_uint2((iy0*WW+ix0) | ((iy0*WW+ix1) << 16),
                              (iy1*WW+ix0) | ((iy1*WW+ix1) << 16));
        g_wgt[g] = make_float4(w00, w01, w10, w11);
    }
}

// ---------------- kernel 2: smem-plane gather -> g_val ----------------
// CTA per (b, 4 h-rows); per channel: stage 64x64 plane in smem, gather via LDS
__global__ __launch_bounds__(256) void k_gather(const float* __restrict__ x)
{
    __shared__ float plane[4096];

    const int t = threadIdx.x;
    const int h0 = blockIdx.x * 4, b = blockIdx.y;
    const int r = t >> 6, w = t & 63;

    // hoist metadata into registers (9 taps for this (r, w))
    uint2  mid[9];
    float4 mwg[9];
    #pragma unroll
    for (int tap = 0; tap < 9; tap++) {
        size_t g = ((size_t)(b * HH + h0 + r) * KK + tap) * WW + w;
        mid[tap] = g_idx[g];
        mwg[tap] = g_wgt[g];
    }

    const float4* xb4 = (const float4*)(x + (size_t)b * CI * HH * WW);
    float* vb = g_val + (size_t)b * CK * 4096;
    const int sbase = (h0 + r) * 64 + w;

    float4 pre[4];
    #pragma unroll
    for (int u = 0; u < 4; u++) pre[u] = xb4[t + u * 256];   // c = 0

    for (int c = 0; c < CI; c++) {
        __syncthreads();                     // plane free
        #pragma unroll
        for (int u = 0; u < 4; u++) ((float4*)plane)[t + u * 256] = pre[u];
        __syncthreads();                     // plane ready
        if (c + 1 < CI) {
            const float4* xn = xb4 + (size_t)(c + 1) * 1024;
            #pragma unroll
            for (int u = 0; u < 4; u++) pre[u] = xn[t + u * 256];
        }
        #pragma unroll
        for (int tap = 0; tap < 9; tap++) {
            uint2 id = mid[tap];
            float4 wg = mwg[tap];
            float v = wg.x * plane[id.x & 0xFFFF] + wg.y * plane[id.x >> 16]
                    + wg.z * plane[id.y & 0xFFFF] + wg.w * plane[id.y >> 16];
            vb[(size_t)(c * 9 + tap) * 4096 + sbase] = to_tf32(v);
        }
    }
}

// ---------------- kernel 3: dense tf32 GEMM ----------------
// CTA per (m-tile 128 s, o-half 128, b): K = 72 chunks x 32, cp.async pipeline
__global__ __launch_bounds__(256, 2) void k_gemm(float* __restrict__ out)
{
    extern __shared__ char smem[];
    float* sA = (float*)smem;                  // [2][32*GSTR], layout [k][m]
    float* sB = (float*)(smem + 2*32*GSTR*4);  // [2][32*GSTR], layout [k][o]

    const int t = threadIdx.x;
    const int mt = blockIdx.x;
    const int bo = blockIdx.y * 128;
    const int b = blockIdx.z;
    const int lane = t & 31, wid = t >> 5;
    const int q = lane >> 2, c2 = lane & 3;
    const int mq = wid & 3, nq = wid >> 2;

    const float* Av = g_val + (size_t)b * CK * 4096 + mt * 128;
    const int sk = t >> 3, sj = t & 7;
    const uint32_t aAbase = smem_u32(sA) + (sk * GSTR + sj * 16) * 4;
    const uint32_t aBbase = smem_u32(sB) + (sk * GSTR + sj * 16) * 4;

    float acc[2][8][4];
    #pragma unroll
    for (int a = 0; a < 2; a++)
        #pragma unroll
        for (int c = 0; c < 8; c++)
            #pragma unroll
            for (int u = 0; u < 4; u++) acc[a][c][u] = 0.f;

    // produce chunk j into buffer j&1
    auto produce = [&](int j) {
        const int p = j & 1;
        const float* ga = Av + (size_t)(j * 32 + sk) * 4096 + sj * 16;
        const float* gb = g_wtT + (size_t)(j * 32 + sk) * 256 + bo + sj * 16;
        uint32_t aA = aAbase + p * (32 * GSTR * 4);
        uint32_t aB = aBbase + p * (32 * GSTR * 4);
        #pragma unroll
        for (int u = 0; u < 4; u++) {
            CP_ASYNC16(aA + u * 16, ga + u * 4);
            CP_ASYNC16(aB + u * 16, gb + u * 4);
        }
    };

    produce(0); CP_COMMIT();

    for (int i = 0; i < NCHUNK; i++) {
        if (i + 1 < NCHUNK) { produce(i + 1); CP_COMMIT(); CP_WAIT1(); }
        else                { CP_WAIT0(); }
        __syncthreads();

        const float* Ab = sA + (i & 1) * (32 * GSTR);
        const float* Bb = sB + (i & 1) * (32 * GSTR);
        #pragma unroll
        for (int ks = 0; ks < 4; ks++) {
            const int krow = (ks * 8 + c2) * GSTR;
            uint32_t af[2][4];
            #pragma unroll
            for (int mi = 0; mi < 2; mi++) {
                int m0 = mq * 32 + mi * 16 + q;
                af[mi][0] = __float_as_uint(Ab[krow + m0]);
                af[mi][1] = __float_as_uint(Ab[krow + m0 + 8]);
                af[mi][2] = __float_as_uint(Ab[krow + 4 * GSTR + m0]);
                af[mi][3] = __float_as_uint(Ab[krow + 4 * GSTR + m0 + 8]);
            }
            uint32_t bf[8][2];
            #pragma unroll
            for (int nj = 0; nj < 8; nj++) {
                int n0 = nq * 64 + nj * 8 + q;
                bf[nj][0] = __float_as_uint(Bb[krow + n0]);
                bf[nj][1] = __float_as_uint(Bb[krow + 4 * GSTR + n0]);
            }
            #pragma unroll
            for (int mi = 0; mi < 2; mi++)
                #pragma unroll
                for (int nj = 0; nj < 8; nj++)
                    mma_tf32(acc[mi][nj], af[mi][0], af[mi][1], af[mi][2], af[mi][3],
                             bf[nj][0], bf[nj][1]);
        }
        __syncthreads();
    }

    // epilogue
    #pragma unroll
    for (int mi = 0; mi < 2; mi++) {
        #pragma unroll
        for (int nj = 0; nj < 8; nj++) {
            int o = bo + nq * 64 + nj * 8 + 2 * c2;
            #pragma unroll
            for (int half = 0; half < 2; half++) {
                int m = mq * 32 + mi * 16 + q + half * 8;
                int s = mt * 128 + m;
                int h = s >> 6, w = s & 63;
                size_t base = (((size_t)b * CO + o) * HH + h) * WW + w;
                out[base]        = acc[mi][nj][half * 2];
                out[base + 4096] = acc[mi][nj][half * 2 + 1];   // o+1
            }
        }
    }
}

// ---------------- launch ----------------
extern "C" void kernel_launch(void* const* d_in, const int* in_sizes, int n_in,
                              void* d_out, int out_size)
{
    const float* x     = (const float*)d_in[0];
    const float* off_w = (const float*)d_in[1];
    const float* off_b = (const float*)d_in[2];
    const float* mod_w = (const float*)d_in[3];
    const float* mod_b = (const float*)d_in[4];
    const float* reg_w = (const float*)d_in[5];
    float* out = (float*)d_out;

    const int gemm_smem = 4 * 32 * GSTR * 4;   // 71680
    cudaFuncSetAttribute(k_gemm, cudaFuncAttributeMaxDynamicSharedMemorySize, gemm_smem);

    k_prep<<<(CK*CO + 255) / 256, 256>>>(reg_w, off_w, mod_w);
    dim3 g1(16, 8);
    k_off<<<g1, 256>>>(x, off_b, mod_b);
    dim3 g2(16, 8);
    k_gather<<<g2, 256>>>(x);
    dim3 g3(32, 2, 8);
    k_gemm<<<g3, 256, gemm_smem>>>(out);
}

// round 10
// speedup vs baseline: 2.2763x; 1.2310x over previous
#include <cuda_runtime.h>
#include <cstdint>

#define HH 64
#define WW 64
#define CI 256
#define CO 256
#define BB 8
#define KK 9
#define CK (CI*KK)      // 2304
#define NCHUNK 72
#define ASTR 40         // k_off smem stride

// k_gemm layout
#define ASTRIDE 136     // 136 % 32 == 8 -> conflict-free frag LDS
#define BSTRIDE 264     // 264 % 32 == 8
#define ABYTES  (32*ASTRIDE*4)          // 17408
#define BBYTES  (32*BSTRIDE*4)          // 33792
#define STGBYTES (ABYTES + BBYTES)      // 51200
#define GEMM_SMEM (4*STGBYTES)          // 204800

// ---------------- scratch (device globals; no allocation) ----------------
__device__ float  g_owt[CK*32];              // tf32 offset/mod weights, [ck][oc-pad32]
__device__ float  g_wtT[CK*CO];              // tf32 reg_w transposed: [ck][o]
__device__ uint2  g_idx[BB*HH*KK*WW];        // packed 4 x u16 corner indices (y*64+x)
__device__ float4 g_wgt[BB*HH*KK*WW];        // 4 bilinear wgts * mask * valid
__device__ float  g_val[(size_t)BB*CK*4096]; // gathered A: [b][ck][s], tf32

// ---------------- helpers ----------------
__device__ __forceinline__ float to_tf32(float x) {
    float r; asm("cvt.rna.tf32.f32 %0, %1;" : "=f"(r) : "f"(x)); return r;
}
__device__ __forceinline__ void mma_tf32(float* d,
    uint32_t a0, uint32_t a1, uint32_t a2, uint32_t a3, uint32_t b0, uint32_t b1) {
    asm volatile("mma.sync.aligned.m16n8k8.row.col.f32.tf32.tf32.f32 "
        "{%0,%1,%2,%3}, {%4,%5,%6,%7}, {%8,%9}, {%0,%1,%2,%3};"
        : "+f"(d[0]), "+f"(d[1]), "+f"(d[2]), "+f"(d[3])
        : "r"(a0), "r"(a1), "r"(a2), "r"(a3), "r"(b0), "r"(b1));
}
__device__ __forceinline__ int div9(int kg) { return (kg * 7282) >> 16; }   // kg < 2304
__device__ __forceinline__ uint32_t smem_u32(const void* p) {
    uint32_t a;
    asm("{ .reg .u64 t; cvta.to.shared.u64 t, %1; cvt.u32.u64 %0, t; }" : "=r"(a) : "l"(p));
    return a;
}
#define CP_ASYNC16(sa, ga) asm volatile("cp.async.cg.shared.global [%0], [%1], 16;" :: "r"(sa), "l"(ga))
#define CP_COMMIT()        asm volatile("cp.async.commit_group;" ::: "memory")
#define CP_WAIT2()         asm volatile("cp.async.wait_group 2;" ::: "memory")
#define CP_WAIT1()         asm volatile("cp.async.wait_group 1;" ::: "memory")
#define CP_WAIT0()         asm volatile("cp.async.wait_group 0;" ::: "memory")

// ---------------- kernel 0: weight prep ----------------
__global__ __launch_bounds__(256) void k_prep(
    const float* __restrict__ reg_w,
    const float* __restrict__ off_w,
    const float* __restrict__ mod_w)
{
    int i = blockIdx.x * 256 + threadIdx.x;
    if (i < CK*CO) {                       // i = ck*256 + o
        int o = i & 255, ck = i >> 8;
        g_wtT[i] = to_tf32(reg_w[o * CK + ck]);
    }
    if (i < CK*32) {
        int oc = i & 31, ck = i >> 5;
        float v = 0.f;
        if (oc < 18)      v = off_w[oc * CK + ck];
        else if (oc < 27) v = mod_w[(oc - 18) * CK + ck];
        g_owt[i] = to_tf32(v);
    }
}

// ---------------- kernel 1: offset/mod conv (tf32 MMA) + sampling metadata ----
__global__ __launch_bounds__(256) void k_off(
    const float* __restrict__ x,
    const float* __restrict__ off_b,
    const float* __restrict__ mod_b)
{
    __shared__ float xs[5*6*68];
    __shared__ float wb[32*ASTR];
    __shared__ float sD[256*28];

    const int t = threadIdx.x;
    const int h0 = blockIdx.x * 4, b = blockIdx.y;
    const int lane = t & 31, wid = t >> 5;
    const int q = lane >> 2, c2 = lane & 3;

    const float* xb = x + (size_t)b * CI * HH * WW;

    float acc[2][4][4];
    #pragma unroll
    for (int a = 0; a < 2; a++)
        #pragma unroll
        for (int c = 0; c < 4; c++)
            #pragma unroll
            for (int u = 0; u < 4; u++) acc[a][c][u] = 0.f;

    for (int i = 0; i < NCHUNK; i++) {
        __syncthreads();
        const int cbase = div9(32 * i);
        #pragma unroll
        for (int j = 0; j < 8; j++) {
            int e = t + j * 256;
            if (e < 5*408) {
                int slot = e / 408, rem = e - slot * 408;
                int row6 = rem / 68, col = rem - row6 * 68;
                int c = cbase + slot;
                int y = h0 - 1 + row6, xc = col - 1;
                float v = 0.f;
                if (c < CI && y >= 0 && y < HH && xc >= 0 && xc < WW)
                    v = xb[((size_t)c * HH + y) * WW + xc];
                xs[e] = v;
            }
        }
        #pragma unroll
        for (int j = 0; j < 4; j++) {
            int e = t + j * 256;
            int k = e >> 5, oc = e & 31;
            wb[k * ASTR + oc] = g_owt[(i * 32 + k) * 32 + oc];
        }
        __syncthreads();

        int aoff[8];
        #pragma unroll
        for (int u = 0; u < 8; u++) {
            int kv = (u >> 1) * 8 + c2 + (u & 1) * 4;
            int kg = i * 32 + kv;
            int c = div9(kg), tap = kg - c * 9;
            int ky = (tap * 11) >> 5, kx = tap - 3 * ky;
            aoff[u] = (c - cbase) * 408 + ky * 68 + kx;
        }

        #pragma unroll
        for (int ks = 0; ks < 4; ks++) {
            uint32_t af[2][4];
            #pragma unroll
            for (int mi = 0; mi < 2; mi++) {
                int m0 = wid * 32 + mi * 16;
                int base = (m0 >> 6) * 68 + (m0 & 63) + q;
                af[mi][0] = __float_as_uint(to_tf32(xs[aoff[2*ks]     + base]));
                af[mi][1] = __float_as_uint(to_tf32(xs[aoff[2*ks]     + base + 8]));
                af[mi][2] = __float_as_uint(to_tf32(xs[aoff[2*ks + 1] + base]));
                af[mi][3] = __float_as_uint(to_tf32(xs[aoff[2*ks + 1] + base + 8]));
            }
            uint32_t bf[4][2];
            #pragma unroll
            for (int nj = 0; nj < 4; nj++) {
                int n = nj * 8 + q;
                bf[nj][0] = __float_as_uint(wb[(8*ks + c2)     * ASTR + n]);
                bf[nj][1] = __float_as_uint(wb[(8*ks + c2 + 4) * ASTR + n]);
            }
            #pragma unroll
            for (int mi = 0; mi < 2; mi++)
                #pragma unroll
                for (int nj = 0; nj < 4; nj++)
                    mma_tf32(acc[mi][nj], af[mi][0], af[mi][1], af[mi][2], af[mi][3],
                             bf[nj][0], bf[nj][1]);
        }
    }

    __syncthreads();
    #pragma unroll
    for (int mi = 0; mi < 2; mi++) {
        #pragma unroll
        for (int nj = 0; nj < 4; nj++) {
            int m = wid * 32 + mi * 16 + q;
            int oc = nj * 8 + 2 * c2;
            if (oc < 28) {
                float b0 = (oc < 18) ? off_b[oc] : ((oc < 27) ? mod_b[oc - 18] : 0.f);
                int oc1 = oc + 1;
                float b1 = (oc1 < 18) ? off_b[oc1] : ((oc1 < 27) ? mod_b[oc1 - 18] : 0.f);
                sD[m * 28 + oc]           = acc[mi][nj][0] + b0;
                if (oc1 < 28) sD[m * 28 + oc1] = acc[mi][nj][1] + b1;
                sD[(m + 8) * 28 + oc]     = acc[mi][nj][2] + b0;
                if (oc1 < 28) sD[(m + 8) * 28 + oc1] = acc[mi][nj][3] + b1;
            }
        }
    }
    __syncthreads();

    #pragma unroll
    for (int j = 0; j < 9; j++) {
        int e = t + j * 256;
        int r = e / 576, rem = e - r * 576;
        int k = rem >> 6, s = rem & 63;
        int m = r * 64 + s;
        float oy = sD[m * 28 + 2*k];
        float ox = sD[m * 28 + 2*k + 1];
        float mm = sD[m * 28 + 18 + k];
        oy = fminf(fmaxf(oy, -16.f), 16.f);
        ox = fminf(fmaxf(ox, -16.f), 16.f);
        mm = 1.f / (1.f + expf(-mm));
        float py = oy + (float)(k / 3) + (float)(h0 + r - 1);
        float px = ox + (float)(k % 3) + (float)(s - 1);
        float y0f = floorf(py), x0f = floorf(px);
        float ly = py - y0f, lx = px - x0f;
        int y0 = (int)y0f, x0 = (int)x0f;
        int y1 = y0 + 1, x1 = x0 + 1;
        float vy0 = (y0 >= 0 && y0 < HH) ? 1.f : 0.f;
        float vy1 = (y1 >= 0 && y1 < HH) ? 1.f : 0.f;
        float vx0 = (x0 >= 0 && x0 < WW) ? 1.f : 0.f;
        float vx1 = (x1 >= 0 && x1 < WW) ? 1.f : 0.f;
        unsigned iy0 = min(max(y0, 0), HH-1), iy1 = min(max(y1, 0), HH-1);
        unsigned ix0 = min(max(x0, 0), WW-1), ix1 = min(max(x1, 0), WW-1);
        float w00 = (1.f-ly)*(1.f-lx)*mm*vy0*vx0;
        float w01 = (1.f-ly)*     lx *mm*vy0*vx1;
        float w10 =      ly *(1.f-lx)*mm*vy1*vx0;
        float w11 =      ly *     lx *mm*vy1*vx1;
        size_t g = ((size_t)(b * HH + h0 + r) * KK + k) * WW + s;
        g_idx[g] = make_uint2((iy0*WW+ix0) | ((iy0*WW+ix1) << 16),
                              (iy1*WW+ix0) | ((iy1*WW+ix1) << 16));
        g_wgt[g] = make_float4(w00, w01, w10, w11);
    }
}

// ---------------- kernel 2: smem-plane gather -> g_val ----------------
__global__ __launch_bounds__(256) void k_gather(const float* __restrict__ x)
{
    __shared__ float plane[4096];

    const int t = threadIdx.x;
    const int h0 = blockIdx.x * 4, b = blockIdx.y;
    const int r = t >> 6, w = t & 63;

    uint2  mid[9];
    float4 mwg[9];
    #pragma unroll
    for (int tap = 0; tap < 9; tap++) {
        size_t g = ((size_t)(b * HH + h0 + r) * KK + tap) * WW + w;
        mid[tap] = g_idx[g];
        mwg[tap] = g_wgt[g];
    }

    const float4* xb4 = (const float4*)(x + (size_t)b * CI * HH * WW);
    float* vb = g_val + (size_t)b * CK * 4096;
    const int sbase = (h0 + r) * 64 + w;

    float4 pre[4];
    #pragma unroll
    for (int u = 0; u < 4; u++) pre[u] = xb4[t + u * 256];

    for (int c = 0; c < CI; c++) {
        __syncthreads();
        #pragma unroll
        for (int u = 0; u < 4; u++) ((float4*)plane)[t + u * 256] = pre[u];
        __syncthreads();
        if (c + 1 < CI) {
            const float4* xn = xb4 + (size_t)(c + 1) * 1024;
            #pragma unroll
            for (int u = 0; u < 4; u++) pre[u] = xn[t + u * 256];
        }
        #pragma unroll
        for (int tap = 0; tap < 9; tap++) {
            uint2 id = mid[tap];
            float4 wg = mwg[tap];
            float v = wg.x * plane[id.x & 0xFFFF] + wg.y * plane[id.x >> 16]
                    + wg.z * plane[id.y & 0xFFFF] + wg.w * plane[id.y >> 16];
            vb[(size_t)(c * 9 + tap) * 4096 + sbase] = to_tf32(v);
        }
    }
}

// ---------------- kernel 3: dense tf32 GEMM v2 ----------------
// CTA per (m-tile 128 s, b): D[m=128][n=256 o], 512 thr, 4-stage cp.async
__global__ __launch_bounds__(512, 1) void k_gemm(float* __restrict__ out)
{
    extern __shared__ char smem[];

    const int t = threadIdx.x;
    const int mt = blockIdx.x;          // 0..31
    const int b  = blockIdx.y;          // 0..7
    const int lane = t & 31, wid = t >> 5;
    const int q = lane >> 2, c2 = lane & 3;
    const int mq = wid & 3, nq = wid >> 2;    // mq: 32-row quad, nq: 64-col quad

    const int rowT = t >> 4, lane16 = t & 15;
    const float* Ag = g_val + (size_t)b * CK * 4096 + mt * 128;
    const uint32_t sbase = smem_u32(smem);
    const uint32_t daBase = sbase + rowT * (ASTRIDE*4) + lane16 * 32;
    const uint32_t dbBase = sbase + ABYTES + rowT * (BSTRIDE*4) + lane16 * 64;

    float acc[2][8][4];
    #pragma unroll
    for (int a = 0; a < 2; a++)
        #pragma unroll
        for (int c = 0; c < 8; c++)
            #pragma unroll
            for (int u = 0; u < 4; u++) acc[a][c][u] = 0.f;

    auto produce = [&](int j) {
        const uint32_t soff = (uint32_t)(j & 3) * STGBYTES;
        const float* ga = Ag + (size_t)(j * 32 + rowT) * 4096 + lane16 * 8;
        const float* gb = g_wtT + (size_t)(j * 32 + rowT) * 256 + lane16 * 16;
        uint32_t da = daBase + soff;
        uint32_t db = dbBase + soff;
        CP_ASYNC16(da,      ga);
        CP_ASYNC16(da + 16, ga + 4);
        #pragma unroll
        for (int u = 0; u < 4; u++) CP_ASYNC16(db + u * 16, gb + u * 4);
    };

    produce(0); CP_COMMIT();
    produce(1); CP_COMMIT();

    for (int i = 0; i < NCHUNK; i++) {
        if (i + 2 < NCHUNK) { produce(i + 2); CP_COMMIT(); CP_WAIT2(); }
        else if (i + 1 < NCHUNK) CP_WAIT1();
        else CP_WAIT0();
        __syncthreads();

        const float* Ab = (const float*)(smem + (i & 3) * STGBYTES);
        const float* Bb = (const float*)(smem + (i & 3) * STGBYTES + ABYTES);
        #pragma unroll
        for (int ks = 0; ks < 4; ks++) {
            const int kr = ks * 8 + c2;
            uint32_t af[2][4];
            #pragma unroll
            for (int mi = 0; mi < 2; mi++) {
                int m0 = mq * 32 + mi * 16 + q;
                af[mi][0] = __float_as_uint(Ab[kr * ASTRIDE + m0]);
                af[mi][1] = __float_as_uint(Ab[kr * ASTRIDE + m0 + 8]);
                af[mi][2] = __float_as_uint(Ab[(kr + 4) * ASTRIDE + m0]);
                af[mi][3] = __float_as_uint(Ab[(kr + 4) * ASTRIDE + m0 + 8]);
            }
            uint32_t bf[8][2];
            #pragma unroll
            for (int nj = 0; nj < 8; nj++) {
                int n0 = nq * 64 + nj * 8 + q;
                bf[nj][0] = __float_as_uint(Bb[kr * BSTRIDE + n0]);
                bf[nj][1] = __float_as_uint(Bb[(kr + 4) * BSTRIDE + n0]);
            }
            #pragma unroll
            for (int mi = 0; mi < 2; mi++)
                #pragma unroll
                for (int nj = 0; nj < 8; nj++)
                    mma_tf32(acc[mi][nj], af[mi][0], af[mi][1], af[mi][2], af[mi][3],
                             bf[nj][0], bf[nj][1]);
        }
    }

    // epilogue
    #pragma unroll
    for (int mi = 0; mi < 2; mi++) {
        #pragma unroll
        for (int nj = 0; nj < 8; nj++) {
            int o = nq * 64 + nj * 8 + 2 * c2;
            #pragma unroll
            for (int half = 0; half < 2; half++) {
                int m = mq * 32 + mi * 16 + q + half * 8;
                int s = mt * 128 + m;
                int h = s >> 6, w = s & 63;
                size_t base = (((size_t)b * CO + o) * HH + h) * WW + w;
                out[base]        = acc[mi][nj][half * 2];
                out[base + 4096] = acc[mi][nj][half * 2 + 1];   // o+1
            }
        }
    }
}

// ---------------- launch ----------------
extern "C" void kernel_launch(void* const* d_in, const int* in_sizes, int n_in,
                              void* d_out, int out_size)
{
    const float* x     = (const float*)d_in[0];
    const float* off_w = (const float*)d_in[1];
    const float* off_b = (const float*)d_in[2];
    const float* mod_w = (const float*)d_in[3];
    const float* mod_b = (const float*)d_in[4];
    const float* reg_w = (const float*)d_in[5];
    float* out = (float*)d_out;

    cudaFuncSetAttribute(k_gemm, cudaFuncAttributeMaxDynamicSharedMemorySize, GEMM_SMEM);

    k_prep<<<(CK*CO + 255) / 256, 256>>>(reg_w, off_w, mod_w);
    dim3 g1(16, 8);
    k_off<<<g1, 256>>>(x, off_b, mod_b);
    dim3 g2(16, 8);
    k_gather<<<g2, 256>>>(x);
    dim3 g3(32, 8);
    k_gemm<<<g3, 512, GEMM_SMEM>>>(out);
}